// round 16
// baseline (speedup 1.0000x reference)
#include <cuda_runtime.h>

#define NN 100000
#define NE 1280000
#define D 64
#define NCHUNK ((NN + 1023) / 1024)  // 98 scan chunks
#define NPB 64                        // nodes per block in sage_layer
#define SMS 66                        // sm row stride (even -> 8B-aligned pairs)

// ---- scratch: module-scope device arrays, referenced ONLY inside kernels ----
// INVARIANT: g_cnt and g_rank are all-zero at kernel_launch entry (zero-init at
// module load; re-zeroed by sage_layer<1>'s epilogue for the next call).
__device__ int    g_cnt[NN];             // in-degree histogram
__device__ int    g_rank[NN];            // per-node fill cursor (within-node rank)
__device__ int    g_ptr[NN];             // CSR offsets, partial (within-chunk excl)
__device__ int    g_srcl[NE];            // CSR source-node list
__device__ int    g_blk[128];            // per-chunk totals
__device__ float4 g_h1_4[NN * D / 4];    // layer-1 hidden
__device__ float4 g_h2_4[NN * D / 4];    // fallback h output
__device__ float4 g_WT4[4 * D * D / 4];  // W1l^T, W1r^T, W2l^T, W2r^T

typedef unsigned long long ull;

__device__ __forceinline__ ull pack2(float f) {
    ull r;
    unsigned u = __float_as_uint(f);
    asm("mov.b64 %0, {%1, %1};" : "=l"(r) : "r"(u));
    return r;
}
__device__ __forceinline__ void ffma2(ull& acc, ull a, ull b) {
    asm("fma.rn.f32x2 %0, %1, %2, %0;" : "+l"(acc) : "l"(a), "l"(b));
}
__device__ __forceinline__ void unpack2(ull v, float& lo, float& hi) {
    unsigned a, b;
    asm("mov.b64 {%0, %1}, %2;" : "=r"(a), "=r"(b) : "l"(v));
    lo = __uint_as_float(a);
    hi = __uint_as_float(b);
}

// int64 edge data (values < 2^31, little-endian) has all odd int32 words == 0.
__device__ __forceinline__ int detect_is64(const int* ei32) {
    int w = 0;
#pragma unroll
    for (int k = 0; k < 8; k++) w |= ei32[2 * k + 1];
    return (w == 0) ? 1 : 0;
}

__device__ __forceinline__ int load_idx(const void* ei, int pos, int is64) {
    if (is64) return (int)__ldg((const long long*)ei + pos);
    return __ldg((const int*)ei + pos);
}

// ---------------------------------------------------------------------------
// launch 0: histogram destination degrees (g_cnt assumed zero on entry)
__global__ void hist_kernel(const void* __restrict__ ei) {
    __shared__ int s64;
    if (threadIdx.x == 0) s64 = detect_is64((const int*)ei);
    __syncthreads();
    int e = blockIdx.x * blockDim.x + threadIdx.x;
    if (e >= NE) return;
    int d = load_idx(ei, NE + e, s64);
    atomicAdd(&g_cnt[d], 1);
}

// launch 1: per-chunk exclusive scan of g_cnt -> g_ptr (partial), totals -> g_blk.
// Extra block (blockIdx == NCHUNK) transposes the 4 weight matrices.
__global__ void scan1_kernel(const float* __restrict__ W1l, const float* __restrict__ W1r,
                             const float* __restrict__ W2l, const float* __restrict__ W2r) {
    if (blockIdx.x == NCHUNK) {
        const float* src[4] = {W1l, W1r, W2l, W2r};
        float* WT = (float*)g_WT4;
        for (int m = 0; m < 4; m++) {
            const float* S = src[m];
            float* T = WT + m * (D * D);
            for (int i2 = threadIdx.x; i2 < D * D; i2 += 1024) {
                int j = i2 >> 6, k = i2 & 63;
                T[k * D + j] = S[i2];
            }
        }
        return;
    }
    int i = blockIdx.x * 1024 + threadIdx.x;
    int v = (i < NN) ? g_cnt[i] : 0;
    int lane = threadIdx.x & 31, wid = threadIdx.x >> 5;
    int sv = v;
#pragma unroll
    for (int o = 1; o < 32; o <<= 1) {
        int n = __shfl_up_sync(0xffffffffu, sv, o);
        if (lane >= o) sv += n;
    }
    __shared__ int ws[32];
    if (lane == 31) ws[wid] = sv;
    __syncthreads();
    if (wid == 0) {
        int wv = ws[lane];
#pragma unroll
        for (int o = 1; o < 32; o <<= 1) {
            int n = __shfl_up_sync(0xffffffffu, wv, o);
            if (lane >= o) wv += n;
        }
        ws[lane] = wv;
    }
    __syncthreads();
    int off = wid ? ws[wid - 1] : 0;
    int incl = sv + off;
    if (i < NN) g_ptr[i] = incl - v;   // exclusive within chunk
    if (threadIdx.x == 1023) g_blk[blockIdx.x] = incl;
}

// launch 2: fill CSR. Each block builds the full 98-chunk exclusive prefix in
// shared, then slot = g_ptr[d] + pre[d>>10] + atomic rank. (g_rank zero on entry)
__global__ void fill_kernel(const void* __restrict__ ei) {
    __shared__ int pre[NCHUNK];
    __shared__ int s64;
    if (threadIdx.x == 0) s64 = detect_is64((const int*)ei);
    if (threadIdx.x >= 32 && threadIdx.x < 32 + NCHUNK)
        pre[threadIdx.x - 32] = g_blk[threadIdx.x - 32];
    __syncthreads();
    if (threadIdx.x == 0) {
        int run = 0;
#pragma unroll 7
        for (int c = 0; c < NCHUNK; c++) { int tv = pre[c]; pre[c] = run; run += tv; }
    }
    __syncthreads();
    int e = blockIdx.x * blockDim.x + threadIdx.x;
    if (e >= NE) return;
    int is64 = s64;
    int s = load_idx(ei, e, is64);
    int d = load_idx(ei, NE + e, is64);
    int base = __ldg(&g_ptr[d]) + pre[d >> 10];
    int r = atomicAdd(&g_rank[d], 1);
    g_srcl[base + r] = s;
}

// ---------------------------------------------------------------------------
// launches 3,4: fused layer. CSR gather-mean + relu(mean @ Wl^T + b + feat @ Wr^T).
// 64 nodes/block, 256 threads. beg = g_ptr[node] + chunk prefix (computed in-block).
// LAYER==1 epilogue zeroes g_cnt/g_rank for this block's nodes (next-call invariant).
template <int LAYER, int HPARAM>
__global__ void __launch_bounds__(256) sage_layer(
                           const float* __restrict__ x,
                           const float* __restrict__ b,
                           float* __restrict__ hout_p,
                           const float* __restrict__ Wh,
                           const float* __restrict__ bh,
                           float* __restrict__ out) {
    __shared__ float smM[D * SMS];   // smM[k*SMS + local_node] : mean
    __shared__ float smX[D * SMS];   // smX[k*SMS + local_node] : root feature
    __shared__ int pre0;
    int t = threadIdx.x;
    int node0 = blockIdx.x * NPB;

    if (t == 0) {   // chunk prefix for this block's (single) 1024-node chunk
        int c0 = node0 >> 10;
        int run = 0;
        for (int c = 0; c < c0; c++) run += __ldg(&g_blk[c]);
        pre0 = run;
    }
    __syncthreads();

    const float* feat = (LAYER == 0) ? x : (const float*)g_h1_4;

    // ---- gather-mean: thread = (node nl, channel-quarter cq) ----
    {
        int nl = t >> 2;          // 0..63
        int cq = t & 3;           // float4 group base: cq*4 .. cq*4+3
        int node = node0 + nl;
        float4 acc[4];
        float4 xv[4];
#pragma unroll
        for (int j = 0; j < 4; j++) {
            acc[j] = make_float4(0.f, 0.f, 0.f, 0.f);
            xv[j] = make_float4(0.f, 0.f, 0.f, 0.f);
        }
        float rd = 0.f;
        if (node < NN) {
            int beg = __ldg(&g_ptr[node]) + pre0;
            int cnt = __ldg(&g_cnt[node]);
            int end = beg + cnt;
            int e = beg;
            for (; e + 1 < end; e += 2) {
                int s0 = __ldg(&g_srcl[e + 0]);
                int s1 = __ldg(&g_srcl[e + 1]);
                const float4* r0 = (const float4*)(feat + (size_t)s0 * D) + cq * 4;
                const float4* r1 = (const float4*)(feat + (size_t)s1 * D) + cq * 4;
#pragma unroll
                for (int j = 0; j < 4; j++) {
                    float4 v0 = __ldg(r0 + j);
                    float4 v1 = __ldg(r1 + j);
                    acc[j].x += v0.x + v1.x;
                    acc[j].y += v0.y + v1.y;
                    acc[j].z += v0.z + v1.z;
                    acc[j].w += v0.w + v1.w;
                }
            }
            if (e < end) {
                int s0 = __ldg(&g_srcl[e]);
                const float4* r0 = (const float4*)(feat + (size_t)s0 * D) + cq * 4;
#pragma unroll
                for (int j = 0; j < 4; j++) {
                    float4 v0 = __ldg(r0 + j);
                    acc[j].x += v0.x; acc[j].y += v0.y;
                    acc[j].z += v0.z; acc[j].w += v0.w;
                }
            }
            rd = 1.0f / (float)max(cnt, 1);
            const float4* rr = (const float4*)(feat + (size_t)node * D) + cq * 4;
#pragma unroll
            for (int j = 0; j < 4; j++) xv[j] = __ldg(rr + j);
        }
#pragma unroll
        for (int j = 0; j < 4; j++) {
            int c = (cq * 4 + j) * 4;
            smM[(c + 0) * SMS + nl] = acc[j].x * rd;
            smM[(c + 1) * SMS + nl] = acc[j].y * rd;
            smM[(c + 2) * SMS + nl] = acc[j].z * rd;
            smM[(c + 3) * SMS + nl] = acc[j].w * rd;
            smX[(c + 0) * SMS + nl] = xv[j].x;
            smX[(c + 1) * SMS + nl] = xv[j].y;
            smX[(c + 2) * SMS + nl] = xv[j].z;
            smX[(c + 3) * SMS + nl] = xv[j].w;
        }
    }
    __syncthreads();

    // ---- linear phase: 4 channels x 4 nodes per thread, f32x2 over node pairs
    int q = t & 15, slot = t >> 4;
    int s4 = slot * 4;
    const float4* wl4 = (const float4*)((const float*)g_WT4 + (2 * LAYER) * (D * D));
    const float4* wr4 = wl4 + (D * D) / 4;
    float4 bb = __ldg((const float4*)b + q);
    ull a0x = pack2(bb.x), a0y = pack2(bb.y), a0z = pack2(bb.z), a0w = pack2(bb.w);
    ull a1x = a0x, a1y = a0y, a1z = a0z, a1w = a0w;

#pragma unroll 4
    for (int k = 0; k < D; k++) {
        float4 wl = __ldg(wl4 + k * 16 + q);
        float4 wr = __ldg(wr4 + k * 16 + q);
        ull wlx = pack2(wl.x), wly = pack2(wl.y), wlz = pack2(wl.z), wlw = pack2(wl.w);
        ull wrx = pack2(wr.x), wry = pack2(wr.y), wrz = pack2(wr.z), wrw = pack2(wr.w);
        ull m0 = *(const ull*)&smM[k * SMS + s4];
        ull m1 = *(const ull*)&smM[k * SMS + s4 + 2];
        ull x0 = *(const ull*)&smX[k * SMS + s4];
        ull x1 = *(const ull*)&smX[k * SMS + s4 + 2];
        ffma2(a0x, wlx, m0); ffma2(a0x, wrx, x0);
        ffma2(a0y, wly, m0); ffma2(a0y, wry, x0);
        ffma2(a0z, wlz, m0); ffma2(a0z, wrz, x0);
        ffma2(a0w, wlw, m0); ffma2(a0w, wrw, x0);
        ffma2(a1x, wlx, m1); ffma2(a1x, wrx, x1);
        ffma2(a1y, wly, m1); ffma2(a1y, wry, x1);
        ffma2(a1z, wlz, m1); ffma2(a1z, wrz, x1);
        ffma2(a1w, wlw, m1); ffma2(a1w, wrw, x1);
    }

    // ---- epilogue: unpack, relu, store h, fused head ----
    float o[4][4];  // [node i][channel j]
    unpack2(a0x, o[0][0], o[1][0]); unpack2(a0y, o[0][1], o[1][1]);
    unpack2(a0z, o[0][2], o[1][2]); unpack2(a0w, o[0][3], o[1][3]);
    unpack2(a1x, o[2][0], o[3][0]); unpack2(a1y, o[2][1], o[3][1]);
    unpack2(a1z, o[2][2], o[3][2]); unpack2(a1w, o[2][3], o[3][3]);
#pragma unroll
    for (int i = 0; i < 4; i++)
#pragma unroll
        for (int j = 0; j < 4; j++) o[i][j] = fmaxf(o[i][j], 0.f);

    float* hout;
    if (LAYER == 0)  hout = (float*)g_h1_4;
    else if (HPARAM) hout = hout_p;
    else             hout = (float*)g_h2_4;

#pragma unroll
    for (int i = 0; i < 4; i++) {
        int node = node0 + s4 + i;
        if (node < NN) {
            float4 v = make_float4(o[i][0], o[i][1], o[i][2], o[i][3]);
            ((float4*)(hout + (size_t)node * D))[q] = v;
        }
    }

    if (LAYER == 1) {
        // head: out[n] = dot(h[n], Wh) + bh, width-16 reduction
        float4 wh = __ldg((const float4*)Wh + q);
        float p[4];
#pragma unroll
        for (int i = 0; i < 4; i++) {
            p[i] = o[i][0] * wh.x + o[i][1] * wh.y + o[i][2] * wh.z + o[i][3] * wh.w;
            p[i] += __shfl_down_sync(0xffffffffu, p[i], 8, 16);
            p[i] += __shfl_down_sync(0xffffffffu, p[i], 4, 16);
            p[i] += __shfl_down_sync(0xffffffffu, p[i], 2, 16);
            p[i] += __shfl_down_sync(0xffffffffu, p[i], 1, 16);
        }
        if (q == 0) {
            float bhv = __ldg(bh);
#pragma unroll
            for (int i = 0; i < 4; i++) {
                int node = node0 + s4 + i;
                if (node < NN) out[node] = p[i] + bhv;
            }
        }
        // restore the next-call invariant: zero g_cnt/g_rank for this block's nodes
        if (t < NPB) {
            int node = node0 + t;
            if (node < NN) { g_cnt[node] = 0; g_rank[node] = 0; }
        }
    }
}

// ---------------------------------------------------------------------------
extern "C" void kernel_launch(void* const* d_in, const int* in_sizes, int n_in,
                              void* d_out, int out_size) {
    const float* x   = (const float*)d_in[0];
    const void*  ei  = d_in[1];
    const float* W1l = (const float*)d_in[2];
    const float* W1r = (const float*)d_in[3];
    const float* b1  = (const float*)d_in[4];
    const float* W2l = (const float*)d_in[5];
    const float* W2r = (const float*)d_in[6];
    const float* b2  = (const float*)d_in[7];
    const float* Wh  = (const float*)d_in[8];
    const float* bh  = (const float*)d_in[9];
    float* outp = (float*)d_out;

    const int EG = (NE + 255) / 256;
    const int LG = (NN + NPB - 1) / NPB;

    hist_kernel<<<EG, 256>>>(ei);                                   // 0
    scan1_kernel<<<NCHUNK + 1, 1024>>>(W1l, W1r, W2l, W2r);         // 1
    fill_kernel<<<EG, 256>>>(ei);                                   // 2
    sage_layer<0, 0><<<LG, 256>>>(x, b1, nullptr, nullptr, nullptr, nullptr);  // 3 <- ncu
    if (out_size >= NN * (D + 1)) {
        sage_layer<1, 1><<<LG, 256>>>(nullptr, b2, outp + NN, Wh, bh, outp);   // 4
    } else {
        sage_layer<1, 0><<<LG, 256>>>(nullptr, b2, nullptr, Wh, bh, outp);
    }
}

// round 17
// speedup vs baseline: 1.4927x; 1.4927x over previous
#include <cuda_runtime.h>

#define NN 100000
#define NE 1280000
#define D 64
#define NCHUNK ((NN + 1023) / 1024)  // 98 scan chunks
#define NPB 64                        // nodes per block in sage_layer
#define SMS 66                        // sm row stride (even -> 8B-aligned pairs)

// ---- scratch: module-scope device arrays, referenced ONLY inside kernels ----
// INVARIANT: g_cnt and g_rank are all-zero at kernel_launch entry (zero-init at
// module load; re-zeroed by sage_layer<1>'s epilogue for the next call).
__device__ int    g_cnt[NN];             // in-degree histogram
__device__ int    g_rank[NN];            // per-node fill cursor
__device__ int    g_ptr[NN];             // CSR offsets (within-chunk exclusive)
__device__ int    g_pre[NCHUNK];         // chunk base offsets (written by fill blk 0)
__device__ int    g_srcl[NE];            // CSR source-node list
__device__ int    g_blk[128];            // per-chunk totals
__device__ float4 g_h1_4[NN * D / 4];    // layer-1 hidden
__device__ float4 g_h2_4[NN * D / 4];    // fallback h output
__device__ float4 g_WT4[4 * D * D / 4];  // W1l^T, W1r^T, W2l^T, W2r^T

typedef unsigned long long ull;

__device__ __forceinline__ ull pack2(float f) {
    ull r;
    unsigned u = __float_as_uint(f);
    asm("mov.b64 %0, {%1, %1};" : "=l"(r) : "r"(u));
    return r;
}
__device__ __forceinline__ void ffma2(ull& acc, ull a, ull b) {
    asm("fma.rn.f32x2 %0, %1, %2, %0;" : "+l"(acc) : "l"(a), "l"(b));
}
__device__ __forceinline__ void unpack2(ull v, float& lo, float& hi) {
    unsigned a, b;
    asm("mov.b64 {%0, %1}, %2;" : "=r"(a), "=r"(b) : "l"(v));
    lo = __uint_as_float(a);
    hi = __uint_as_float(b);
}

// int64 edge data (values < 2^31, little-endian) has all odd int32 words == 0.
__device__ __forceinline__ int detect_is64(const int* ei32) {
    int w = 0;
#pragma unroll
    for (int k = 0; k < 8; k++) w |= ei32[2 * k + 1];
    return (w == 0) ? 1 : 0;
}

__device__ __forceinline__ int load_idx(const void* ei, int pos, int is64) {
    if (is64) return (int)__ldg((const long long*)ei + pos);
    return __ldg((const int*)ei + pos);
}

// ---------------------------------------------------------------------------
// launch 0: histogram destination degrees (g_cnt zero on entry)
__global__ void hist_kernel(const void* __restrict__ ei) {
    __shared__ int s64;
    if (threadIdx.x == 0) s64 = detect_is64((const int*)ei);
    __syncthreads();
    int e = blockIdx.x * blockDim.x + threadIdx.x;
    if (e >= NE) return;
    int d = load_idx(ei, NE + e, s64);
    atomicAdd(&g_cnt[d], 1);
}

// launch 1: per-chunk exclusive scan of g_cnt -> g_ptr, totals -> g_blk.
// Extra block (blockIdx == NCHUNK) transposes the 4 weight matrices.
__global__ void scan1_kernel(const float* __restrict__ W1l, const float* __restrict__ W1r,
                             const float* __restrict__ W2l, const float* __restrict__ W2r) {
    if (blockIdx.x == NCHUNK) {
        const float* src[4] = {W1l, W1r, W2l, W2r};
        float* WT = (float*)g_WT4;
        for (int m = 0; m < 4; m++) {
            const float* S = src[m];
            float* T = WT + m * (D * D);
            for (int i2 = threadIdx.x; i2 < D * D; i2 += 1024) {
                int j = i2 >> 6, k = i2 & 63;
                T[k * D + j] = S[i2];
            }
        }
        return;
    }
    int i = blockIdx.x * 1024 + threadIdx.x;
    int v = (i < NN) ? g_cnt[i] : 0;
    int lane = threadIdx.x & 31, wid = threadIdx.x >> 5;
    int sv = v;
#pragma unroll
    for (int o = 1; o < 32; o <<= 1) {
        int n = __shfl_up_sync(0xffffffffu, sv, o);
        if (lane >= o) sv += n;
    }
    __shared__ int ws[32];
    if (lane == 31) ws[wid] = sv;
    __syncthreads();
    if (wid == 0) {
        int wv = ws[lane];
#pragma unroll
        for (int o = 1; o < 32; o <<= 1) {
            int n = __shfl_up_sync(0xffffffffu, wv, o);
            if (lane >= o) wv += n;
        }
        ws[lane] = wv;
    }
    __syncthreads();
    int off = wid ? ws[wid - 1] : 0;
    int incl = sv + off;
    if (i < NN) g_ptr[i] = incl - v;   // exclusive within chunk
    if (threadIdx.x == 1023) g_blk[blockIdx.x] = incl;
}

// launch 2: fill CSR. Each block builds the 98-chunk exclusive prefix in shared;
// block 0 also publishes it to g_pre for the sage kernels.
__global__ void fill_kernel(const void* __restrict__ ei) {
    __shared__ int pre[NCHUNK];
    __shared__ int s64;
    if (threadIdx.x == 0) s64 = detect_is64((const int*)ei);
    if (threadIdx.x >= 32 && threadIdx.x < 32 + NCHUNK)
        pre[threadIdx.x - 32] = g_blk[threadIdx.x - 32];
    __syncthreads();
    if (threadIdx.x == 0) {
        int run = 0;
#pragma unroll 7
        for (int c = 0; c < NCHUNK; c++) { int tv = pre[c]; pre[c] = run; run += tv; }
    }
    __syncthreads();
    if (blockIdx.x == 0 && threadIdx.x < NCHUNK) g_pre[threadIdx.x] = pre[threadIdx.x];
    int e = blockIdx.x * blockDim.x + threadIdx.x;
    if (e >= NE) return;
    int is64 = s64;
    int s = load_idx(ei, e, is64);
    int d = load_idx(ei, NE + e, is64);
    int base = __ldg(&g_ptr[d]) + pre[d >> 10];
    int r = atomicAdd(&g_rank[d], 1);
    g_srcl[base + r] = s;
}

// ---------------------------------------------------------------------------
// launches 3,4: fused layer. 64 nodes/block, 256 threads = 8 warps.
// GATHER: warp-per-node, 8 nodes/warp sequential. Two edges per instruction:
//   lanes 0-15 read edge A's 256B row, lanes 16-31 edge B's -> 4 full 128B
//   wavefronts per 512B (100% line utilization). Cross-half shfl_xor merge.
// LINEAR: 16 channel-groups x 16 slots; 4 nodes/thread, packed f32x2 FMA.
template <int LAYER, int HPARAM>
__global__ void __launch_bounds__(256) sage_layer(
                           const float* __restrict__ x,
                           const float* __restrict__ b,
                           float* __restrict__ hout_p,
                           const float* __restrict__ Wh,
                           const float* __restrict__ bh,
                           float* __restrict__ out) {
    __shared__ float smM[D * SMS];   // smM[k*SMS + local_node] : mean
    __shared__ float smX[D * SMS];   // smX[k*SMS + local_node] : root feature
    __shared__ int pre0;
    int t = threadIdx.x;
    int node0 = blockIdx.x * NPB;
    if (t == 0) pre0 = __ldg(&g_pre[node0 >> 10]);  // block spans one 1024-chunk
    __syncthreads();

    const float* feat = (LAYER == 0) ? x : (const float*)g_h1_4;

    // ---- gather-mean: warp per node, 8 nodes per warp ----
    {
        int warp = t >> 5, lane = t & 31;
        int half = lane >> 4, li = lane & 15;
#pragma unroll
        for (int i = 0; i < 8; i++) {
            int nl = warp * 8 + i;
            int node = node0 + nl;
            float4 acc = make_float4(0.f, 0.f, 0.f, 0.f);
            float4 xv = make_float4(0.f, 0.f, 0.f, 0.f);
            float rd = 0.f;
            if (node < NN) {                       // warp-uniform branch
                int beg = __ldg(&g_ptr[node]) + pre0;
                int cnt = __ldg(&g_cnt[node]);
                int end = beg + cnt;
                int e = beg;
                for (; e + 3 < end; e += 4) {      // 4 edges/iter, 2 loads in flight
                    int sA = __ldg(&g_srcl[e + half]);
                    int sB = __ldg(&g_srcl[e + 2 + half]);
                    float4 vA = __ldg((const float4*)(feat + (size_t)sA * D) + li);
                    float4 vB = __ldg((const float4*)(feat + (size_t)sB * D) + li);
                    acc.x += vA.x + vB.x; acc.y += vA.y + vB.y;
                    acc.z += vA.z + vB.z; acc.w += vA.w + vB.w;
                }
                if (e + 1 < end) {                 // 2-edge tail
                    int sA = __ldg(&g_srcl[e + half]);
                    float4 vA = __ldg((const float4*)(feat + (size_t)sA * D) + li);
                    acc.x += vA.x; acc.y += vA.y; acc.z += vA.z; acc.w += vA.w;
                    e += 2;
                }
                if (e < end && half == 0) {        // odd single edge: half 0 only
                    int sA = __ldg(&g_srcl[e]);
                    float4 vA = __ldg((const float4*)(feat + (size_t)sA * D) + li);
                    acc.x += vA.x; acc.y += vA.y; acc.z += vA.z; acc.w += vA.w;
                }
                // merge the two half-warp edge sums
                acc.x += __shfl_xor_sync(0xffffffffu, acc.x, 16);
                acc.y += __shfl_xor_sync(0xffffffffu, acc.y, 16);
                acc.z += __shfl_xor_sync(0xffffffffu, acc.z, 16);
                acc.w += __shfl_xor_sync(0xffffffffu, acc.w, 16);
                rd = 1.0f / (float)max(cnt, 1);
                xv = __ldg((const float4*)(feat + (size_t)node * D) + li);
            }
            if (half == 0) {
                int c = li * 4;
                smM[(c + 0) * SMS + nl] = acc.x * rd;
                smM[(c + 1) * SMS + nl] = acc.y * rd;
                smM[(c + 2) * SMS + nl] = acc.z * rd;
                smM[(c + 3) * SMS + nl] = acc.w * rd;
                smX[(c + 0) * SMS + nl] = xv.x;
                smX[(c + 1) * SMS + nl] = xv.y;
                smX[(c + 2) * SMS + nl] = xv.z;
                smX[(c + 3) * SMS + nl] = xv.w;
            }
        }
    }
    __syncthreads();

    // ---- linear phase: 4 channels x 4 nodes per thread, f32x2 over node pairs
    int q = t & 15, slot = t >> 4;
    int s4 = slot * 4;
    const float4* wl4 = (const float4*)((const float*)g_WT4 + (2 * LAYER) * (D * D));
    const float4* wr4 = wl4 + (D * D) / 4;
    float4 bb = __ldg((const float4*)b + q);
    ull a0x = pack2(bb.x), a0y = pack2(bb.y), a0z = pack2(bb.z), a0w = pack2(bb.w);
    ull a1x = a0x, a1y = a0y, a1z = a0z, a1w = a0w;

#pragma unroll 4
    for (int k = 0; k < D; k++) {
        float4 wl = __ldg(wl4 + k * 16 + q);
        float4 wr = __ldg(wr4 + k * 16 + q);
        ull wlx = pack2(wl.x), wly = pack2(wl.y), wlz = pack2(wl.z), wlw = pack2(wl.w);
        ull wrx = pack2(wr.x), wry = pack2(wr.y), wrz = pack2(wr.z), wrw = pack2(wr.w);
        ull m0 = *(const ull*)&smM[k * SMS + s4];
        ull m1 = *(const ull*)&smM[k * SMS + s4 + 2];
        ull x0 = *(const ull*)&smX[k * SMS + s4];
        ull x1 = *(const ull*)&smX[k * SMS + s4 + 2];
        ffma2(a0x, wlx, m0); ffma2(a0x, wrx, x0);
        ffma2(a0y, wly, m0); ffma2(a0y, wry, x0);
        ffma2(a0z, wlz, m0); ffma2(a0z, wrz, x0);
        ffma2(a0w, wlw, m0); ffma2(a0w, wrw, x0);
        ffma2(a1x, wlx, m1); ffma2(a1x, wrx, x1);
        ffma2(a1y, wly, m1); ffma2(a1y, wry, x1);
        ffma2(a1z, wlz, m1); ffma2(a1z, wrz, x1);
        ffma2(a1w, wlw, m1); ffma2(a1w, wrw, x1);
    }

    // ---- epilogue: unpack, relu, store h, fused head ----
    float o[4][4];  // [node i][channel j]
    unpack2(a0x, o[0][0], o[1][0]); unpack2(a0y, o[0][1], o[1][1]);
    unpack2(a0z, o[0][2], o[1][2]); unpack2(a0w, o[0][3], o[1][3]);
    unpack2(a1x, o[2][0], o[3][0]); unpack2(a1y, o[2][1], o[3][1]);
    unpack2(a1z, o[2][2], o[3][2]); unpack2(a1w, o[2][3], o[3][3]);
#pragma unroll
    for (int i = 0; i < 4; i++)
#pragma unroll
        for (int j = 0; j < 4; j++) o[i][j] = fmaxf(o[i][j], 0.f);

    float* hout;
    if (LAYER == 0)  hout = (float*)g_h1_4;
    else if (HPARAM) hout = hout_p;
    else             hout = (float*)g_h2_4;

#pragma unroll
    for (int i = 0; i < 4; i++) {
        int node = node0 + s4 + i;
        if (node < NN) {
            float4 v = make_float4(o[i][0], o[i][1], o[i][2], o[i][3]);
            ((float4*)(hout + (size_t)node * D))[q] = v;
        }
    }

    if (LAYER == 1) {
        // head: out[n] = dot(h[n], Wh) + bh, width-16 reduction
        float4 wh = __ldg((const float4*)Wh + q);
        float p[4];
#pragma unroll
        for (int i = 0; i < 4; i++) {
            p[i] = o[i][0] * wh.x + o[i][1] * wh.y + o[i][2] * wh.z + o[i][3] * wh.w;
            p[i] += __shfl_down_sync(0xffffffffu, p[i], 8, 16);
            p[i] += __shfl_down_sync(0xffffffffu, p[i], 4, 16);
            p[i] += __shfl_down_sync(0xffffffffu, p[i], 2, 16);
            p[i] += __shfl_down_sync(0xffffffffu, p[i], 1, 16);
        }
        if (q == 0) {
            float bhv = __ldg(bh);
#pragma unroll
            for (int i = 0; i < 4; i++) {
                int node = node0 + s4 + i;
                if (node < NN) out[node] = p[i] + bhv;
            }
        }
        // restore next-call invariant: zero g_cnt/g_rank for this block's nodes
        if (t < NPB) {
            int node = node0 + t;
            if (node < NN) { g_cnt[node] = 0; g_rank[node] = 0; }
        }
    }
}

// ---------------------------------------------------------------------------
extern "C" void kernel_launch(void* const* d_in, const int* in_sizes, int n_in,
                              void* d_out, int out_size) {
    const float* x   = (const float*)d_in[0];
    const void*  ei  = d_in[1];
    const float* W1l = (const float*)d_in[2];
    const float* W1r = (const float*)d_in[3];
    const float* b1  = (const float*)d_in[4];
    const float* W2l = (const float*)d_in[5];
    const float* W2r = (const float*)d_in[6];
    const float* b2  = (const float*)d_in[7];
    const float* Wh  = (const float*)d_in[8];
    const float* bh  = (const float*)d_in[9];
    float* outp = (float*)d_out;

    const int EG = (NE + 255) / 256;
    const int LG = (NN + NPB - 1) / NPB;

    hist_kernel<<<EG, 256>>>(ei);                                   // 0
    scan1_kernel<<<NCHUNK + 1, 1024>>>(W1l, W1r, W2l, W2r);         // 1
    fill_kernel<<<EG, 256>>>(ei);                                   // 2
    sage_layer<0, 0><<<LG, 256>>>(x, b1, nullptr, nullptr, nullptr, nullptr);  // 3 <- ncu
    if (out_size >= NN * (D + 1)) {
        sage_layer<1, 1><<<LG, 256>>>(nullptr, b2, outp + NN, Wh, bh, outp);   // 4
    } else {
        sage_layer<1, 0><<<LG, 256>>>(nullptr, b2, nullptr, Wh, bh, outp);
    }
}